// round 16
// baseline (speedup 1.0000x reference)
#include <cuda_runtime.h>
#include <cuda_fp16.h>
#include <math.h>
#include <cstdint>

// ---------------- problem constants ----------------
constexpr int BATCH = 2;
constexpr int SEQ   = 4096;
constexpr int DM    = 768;
constexpr int NH    = 12;
constexpr int DHD   = 64;
constexpr int NL    = 12;
constexpr int WW    = 256;
constexpr int FFD   = 3072;
constexpr int HIDN  = 384;
constexpr int NCH   = SEQ / WW;          // 16 chunks
constexpr int NROWS = BATCH * SEQ;       // 8192
constexpr int W3    = 3 * WW;            // 768
constexpr int QKVS  = 3 * DM;            // 2304 row stride of fused qkv

// ---------------- device scratch (static: no allocation allowed) ----------------
__device__ float g_h  [NROWS * DM];
__device__ __align__(16) __half g_hr [NROWS * DM];       // fp16 copy of h (GEMM A)
__device__ __align__(16) __half g_qkv[NROWS * QKVS];     // fused q|k|v fp16
__device__ __align__(16) __half g_ctx[NROWS * DM];
__device__ __align__(16) __half g_p  [(size_t)BATCH * NH * NCH * WW * W3];  // probs fp16
__device__ __align__(16) __half g_ffh[NROWS * FFD];      // FF hidden fp16
__device__ float g_t  [NROWS * DM];
__device__ float g_xf [NROWS * 4 * HIDN];
__device__ float g_xb [NROWS * 4 * HIDN];
__device__ __align__(16) __half g_wTh[FFD * DM];         // transposed fp16 weights
__device__ float g_bqkv[QKVS];
__device__ unsigned char g_mask[NROWS];
__device__ float g_lh [2][2][2 * HIDN];
__device__ unsigned int g_bar[2];

// ---------------- helpers ----------------
__device__ __forceinline__ float sigmoidf_(float x) { return 1.f / (1.f + expf(-x)); }
__device__ __forceinline__ float geluf_(float x)    { return 0.5f * x * (1.f + erff(x * 0.70710678118654752f)); }

__device__ __forceinline__ uint32_t smem_u32(const void* p) {
    uint32_t a;
    asm("{ .reg .u64 t; cvta.to.shared.u64 t, %1; cvt.u32.u64 %0, t; }" : "=r"(a) : "l"(p));
    return a;
}
__device__ __forceinline__ void cp16(uint32_t daddr, const void* src) {
    asm volatile("cp.async.cg.shared.global [%0], [%1], 16;" :: "r"(daddr), "l"(src));
}
__device__ __forceinline__ void ldsm_x4(uint32_t& r0, uint32_t& r1, uint32_t& r2, uint32_t& r3,
                                        uint32_t addr) {
    asm volatile("ldmatrix.sync.aligned.m8n8.x4.shared.b16 {%0,%1,%2,%3}, [%4];"
                 : "=r"(r0), "=r"(r1), "=r"(r2), "=r"(r3) : "r"(addr));
}

__device__ __forceinline__ void mma_f16(float c[4], const uint32_t a[4], const uint32_t b[2]) {
    asm volatile(
        "mma.sync.aligned.m16n8k16.row.col.f32.f16.f16.f32 "
        "{%0,%1,%2,%3}, {%4,%5,%6,%7}, {%8,%9}, {%0,%1,%2,%3};"
        : "+f"(c[0]), "+f"(c[1]), "+f"(c[2]), "+f"(c[3])
        : "r"(a[0]), "r"(a[1]), "r"(a[2]), "r"(a[3]), "r"(b[0]), "r"(b[1]));
}

__device__ __forceinline__ float block_sum256(float v, float* red) {
    #pragma unroll
    for (int o = 16; o; o >>= 1) v += __shfl_xor_sync(0xffffffffu, v, o);
    if ((threadIdx.x & 31) == 0) red[threadIdx.x >> 5] = v;
    __syncthreads();
    float r = red[0] + red[1] + red[2] + red[3] + red[4] + red[5] + red[6] + red[7];
    __syncthreads();
    return r;
}

// ---------------- embedding + layernorm + key_mask ----------------
__global__ void embed_ln_kernel(const int* __restrict__ x, const float* __restrict__ ew,
                                const float* __restrict__ ep, const float* __restrict__ gam,
                                const float* __restrict__ bet) {
    __shared__ float red[8];
    int row = blockIdx.x;
    int tid = threadIdx.x;
    int s = row % SEQ;
    int tok = x[row];
    if (tid == 0) g_mask[row] = (tok != 0) ? 1 : 0;
    float v[3];
    #pragma unroll
    for (int i = 0; i < 3; i++) {
        int c = i * 256 + tid;
        v[i] = ew[(size_t)tok * DM + c] + ep[(size_t)s * DM + c];
    }
    float mean = block_sum256(v[0] + v[1] + v[2], red) * (1.f / DM);
    float var = 0.f;
    #pragma unroll
    for (int i = 0; i < 3; i++) { float d = v[i] - mean; var += d * d; }
    var = block_sum256(var, red) * (1.f / DM);
    float rstd = rsqrtf(var + 1e-5f);
    #pragma unroll
    for (int i = 0; i < 3; i++) {
        int c = i * 256 + tid;
        float o = (v[i] - mean) * rstd * gam[c] + bet[c];
        g_h [(size_t)row * DM + c] = o;
        g_hr[(size_t)row * DM + c] = __float2half_rn(o);
    }
}

// ---------------- residual + layernorm ----------------
__global__ void ln_res_kernel(const float* __restrict__ t, const float* __restrict__ gam,
                              const float* __restrict__ bet) {
    __shared__ float red[8];
    int row = blockIdx.x;
    int tid = threadIdx.x;
    float v[3];
    #pragma unroll
    for (int i = 0; i < 3; i++) {
        int c = i * 256 + tid;
        size_t idx = (size_t)row * DM + c;
        v[i] = g_h[idx] + t[idx];
    }
    float mean = block_sum256(v[0] + v[1] + v[2], red) * (1.f / DM);
    float var = 0.f;
    #pragma unroll
    for (int i = 0; i < 3; i++) { float d = v[i] - mean; var += d * d; }
    var = block_sum256(var, red) * (1.f / DM);
    float rstd = rsqrtf(var + 1e-5f);
    #pragma unroll
    for (int i = 0; i < 3; i++) {
        int c = i * 256 + tid;
        float o = (v[i] - mean) * rstd * gam[c] + bet[c];
        g_h [(size_t)row * DM + c] = o;
        g_hr[(size_t)row * DM + c] = __float2half_rn(o);
    }
}

// ---------------- weight transpose: float in[R][C] -> half out[C][R] ----------------
__global__ void transpose_kernel(const float* __restrict__ in, __half* __restrict__ out,
                                 int R, int C) {
    __shared__ float t[32][33];
    int c0 = blockIdx.x * 32, r0 = blockIdx.y * 32;
    int x = threadIdx.x, y = threadIdx.y;
    #pragma unroll
    for (int i = 0; i < 32; i += 8)
        t[y + i][x] = in[(size_t)(r0 + y + i) * C + c0 + x];
    __syncthreads();
    #pragma unroll
    for (int i = 0; i < 32; i += 8)
        out[(size_t)(c0 + y + i) * R + r0 + x] = __float2half_rn(t[x][y + i]);
}

// ---------------- float -> half copy (LSTM Wi) ----------------
__global__ void halfcopy_kernel(const float* __restrict__ in, __half* __restrict__ out, int n4) {
    int i = blockIdx.x * 256 + threadIdx.x;
    if (i < n4) {
        float4 v = ((const float4*)in)[i];
        __half2* o = (__half2*)out + i * 2;
        o[0] = __floats2half2_rn(v.x, v.y);
        o[1] = __floats2half2_rn(v.z, v.w);
    }
}

// ---------------- bias concat for fused QKV ----------------
__global__ void biascat_kernel(const float* __restrict__ a, const float* __restrict__ b,
                               const float* __restrict__ c) {
    int i = blockIdx.x * 256 + threadIdx.x;
    if (i < DM) g_bqkv[i] = a[i];
    else if (i < 2 * DM) g_bqkv[i] = b[i - DM];
    else if (i < 3 * DM) g_bqkv[i] = c[i - 2 * DM];
}

// ---------------- cp.async 3-stage fp16 GEMM, 128x256 tile, 512 threads ----------------
constexpr int GPITCH = 36;                             // words per 64-half row
constexpr int GAROWS = 128, GBROWS = 256;
constexpr int GSTAGE_U32 = (GAROWS + GBROWS) * GPITCH; // 13824 words per stage
constexpr int GSTG = 3;
constexpr int GTC_SMEM = GSTG * GSTAGE_U32 * 4;        // 165888 B

__global__ void __launch_bounds__(512, 1) gemm_tc_kernel(
    const __half* __restrict__ A, const __half* __restrict__ BT,
    const float* __restrict__ bias, void* __restrict__ Cv,
    int M, int N, int K, int act, int outh) {
    extern __shared__ uint32_t sm[];
    const uint32_t sb = smem_u32(sm);

    const int tid = threadIdx.x;
    const int wid = tid >> 5, lane = tid & 31;
    const int wm = wid & 3, wn = wid >> 2;          // 4 m-warps x 4 n-warps
    const int lr = lane >> 2, lc = lane & 3;
    const int m0 = blockIdx.y * 128, n0 = blockIdx.x * 256;
    const int KT = K / 64;

    // loaders
    const int alrow = tid >> 2, alseg = tid & 3;    // A: 128 rows, 16 halves each (2 cp16)
    const int blrow = tid >> 1, blseg = tid & 1;    // B: 256 rows, 32 halves each (4 cp16)

    // ldmatrix lane->row maps (warp tile 32x64, unchanged)
    const int arow  = wm * 32 + (lane & 15);
    const int acolw = (lane >> 4) * 4;
    const int bg    = lane >> 3;
    const int brow  = wn * 64 + (bg >> 1) * 8 + (lane & 7);
    const int bcolw = (bg & 1) * 4;

    const __half* gA = A + (size_t)(m0 + alrow) * K + alseg * 16;
    const __half* gB = BT + (size_t)(n0 + blrow) * K + blseg * 32;

    #define GISSUE(st, kt) do {                                                   \
        uint32_t base_ = sb + (uint32_t)(st) * (GSTAGE_U32 * 4);                  \
        int kb_ = (kt) * 64;                                                      \
        cp16(base_ + (uint32_t)((alrow * GPITCH + alseg * 8 + 0) * 4), gA + kb_);     \
        cp16(base_ + (uint32_t)((alrow * GPITCH + alseg * 8 + 4) * 4), gA + kb_ + 8); \
        _Pragma("unroll")                                                         \
        for (int i_ = 0; i_ < 4; i_++)                                            \
            cp16(base_ + (uint32_t)((GAROWS * GPITCH + blrow * GPITCH + blseg * 16 + i_ * 4) * 4), \
                 gB + kb_ + i_ * 8);                                              \
        } while (0)

    GISSUE(0, 0);
    asm volatile("cp.async.commit_group;" ::: "memory");
    GISSUE(1, 1);
    asm volatile("cp.async.commit_group;" ::: "memory");

    float acc[2][8][4] = {};
    for (int kt = 0; kt < KT; kt++) {
        asm volatile("cp.async.wait_group 1;" ::: "memory");
        __syncthreads();
        if (kt + 2 < KT) {
            int st = kt + 2; st -= (st / GSTG) * GSTG;
            GISSUE(st, kt + 2);
        }
        asm volatile("cp.async.commit_group;" ::: "memory");

        int cs = kt; cs -= (cs / GSTG) * GSTG;
        const uint32_t abase = sb + (uint32_t)(cs * GSTAGE_U32) * 4;
        const uint32_t bbase = abase + (uint32_t)(GAROWS * GPITCH) * 4;
        #pragma unroll
        for (int kk = 0; kk < 4; kk++) {
            const int kb = kk * 8;
            uint32_t afr[2][4];
            #pragma unroll
            for (int mf = 0; mf < 2; mf++)
                ldsm_x4(afr[mf][0], afr[mf][1], afr[mf][2], afr[mf][3],
                        abase + (uint32_t)(((arow + mf * 16) * GPITCH + kb + acolw) * 4));
            #pragma unroll
            for (int p = 0; p < 4; p++) {
                uint32_t b0, b1, b2, b3;
                ldsm_x4(b0, b1, b2, b3,
                        bbase + (uint32_t)(((brow + p * 16) * GPITCH + kb + bcolw) * 4));
                uint32_t bfr0[2] = { b0, b1 };
                uint32_t bfr1[2] = { b2, b3 };
                mma_f16(acc[0][p * 2 + 0], afr[0], bfr0);
                mma_f16(acc[1][p * 2 + 0], afr[1], bfr0);
                mma_f16(acc[0][p * 2 + 1], afr[0], bfr1);
                mma_f16(acc[1][p * 2 + 1], afr[1], bfr1);
            }
        }
    }
    #undef GISSUE

    // ---- epilogue ----
    #pragma unroll
    for (int mf = 0; mf < 2; mf++) {
        #pragma unroll
        for (int nf = 0; nf < 8; nf++) {
            int row0 = m0 + wm * 32 + mf * 16 + lr;
            int col  = n0 + wn * 64 + nf * 8 + lc * 2;
            float b0 = bias ? bias[col] : 0.f;
            float b1 = bias ? bias[col + 1] : 0.f;
            float2 v0 = make_float2(acc[mf][nf][0] + b0, acc[mf][nf][1] + b1);
            float2 v1 = make_float2(acc[mf][nf][2] + b0, acc[mf][nf][3] + b1);
            if (act) {
                v0.x = geluf_(v0.x); v0.y = geluf_(v0.y);
                v1.x = geluf_(v1.x); v1.y = geluf_(v1.y);
            }
            if (outh) {
                __half* C = (__half*)Cv;
                *(__half2*)(C + (size_t)row0 * N + col) = __floats2half2_rn(v0.x, v0.y);
                *(__half2*)(C + (size_t)(row0 + 8) * N + col) = __floats2half2_rn(v1.x, v1.y);
            } else {
                float* C = (float*)Cv;
                *(float2*)(C + (size_t)row0 * N + col) = v0;
                *(float2*)(C + (size_t)(row0 + 8) * N + col) = v1;
            }
        }
    }
}

// ---------------- fused scores + softmax: 64-row tile, full 768-wide row in smem ----------------
constexpr int SPITCH = 36;                   // words per 64-half row (Q/K tiles)
constexpr int SP3H   = 776;                  // halves pitch of S rows (768 + 8)
constexpr int SSM_SMEM = (64 * SPITCH + 128 * SPITCH) * 4 + 64 * SP3H * 2;  // 126976 B

__global__ void __launch_bounds__(256, 1) scores_sm_kernel() {
    extern __shared__ uint32_t smq[];
    uint32_t* Qw = smq;
    uint32_t* Kw = smq + 64 * SPITCH;
    __half*  S  = (__half*)(smq + 64 * SPITCH + 128 * SPITCH);

    const int cid = blockIdx.y;
    const int bb = cid / (NH * NCH);
    const int hh = (cid / NCH) % NH;
    const int cc = cid % NCH;
    const int m0 = blockIdx.x * 64;
    const int tid = threadIdx.x;
    const int wid = tid >> 5, lane = tid & 31;
    const int wm = wid & 3, wn = wid >> 2;
    const int lr = lane >> 2, lc = lane & 3;

    const int arow  = wm * 16 + (lane & 15);
    const int acolw = (lane >> 4) * 4;
    const int bg    = lane >> 3;
    const int browb = wn * 64 + (bg >> 1) * 8 + (lane & 7);
    const int bcolw = (bg & 1) * 4;
    const uint32_t qb  = smem_u32(Qw);
    const uint32_t kbb = smem_u32(Kw);

    {
        int row = tid >> 2, seg = tid & 3;
        const __half* src = g_qkv + (size_t)(bb * SEQ + cc * WW + m0 + row) * QKVS + hh * DHD + seg * 16;
        uint4 v0 = *(const uint4*)(src);
        uint4 v1 = *(const uint4*)(src + 8);
        *(uint4*)(&Qw[row * SPITCH + seg * 8 + 0]) = v0;
        *(uint4*)(&Qw[row * SPITCH + seg * 8 + 4]) = v1;
    }

    for (int c6 = 0; c6 < 6; c6++) {
        if (c6 > 0) __syncthreads();
        {
            int krow = tid >> 1;
            int kq = (tid & 1) * 16;
            int kpos = cc * WW + c6 * 128 + krow - WW;
            bool in = (kpos >= 0 && kpos < SEQ);
            const __half* src = g_qkv + (size_t)(bb * SEQ + (in ? kpos : 0)) * QKVS + DM + hh * DHD + (tid & 1) * 32;
            #pragma unroll
            for (int i = 0; i < 4; i++) {
                uint4 v = in ? *(const uint4*)(src + i * 8) : make_uint4(0, 0, 0, 0);
                *(uint4*)(&Kw[krow * SPITCH + kq + i * 4]) = v;
            }
        }
        __syncthreads();

        float acc[8][4] = {};
        #pragma unroll
        for (int kk = 0; kk < 4; kk++) {
            const int kb = kk * 8;
            uint32_t afr[4];
            ldsm_x4(afr[0], afr[1], afr[2], afr[3],
                    qb + (uint32_t)((arow * SPITCH + kb + acolw) * 4));
            #pragma unroll
            for (int p = 0; p < 4; p++) {
                uint32_t b0, b1, b2, b3;
                ldsm_x4(b0, b1, b2, b3,
                        kbb + (uint32_t)(((browb + p * 16) * SPITCH + kb + bcolw) * 4));
                uint32_t bfr0[2] = { b0, b1 };
                uint32_t bfr1[2] = { b2, b3 };
                mma_f16(acc[p * 2 + 0], afr, bfr0);
                mma_f16(acc[p * 2 + 1], afr, bfr1);
            }
        }

        #pragma unroll
        for (int nf = 0; nf < 8; nf++) {
            int jl0 = wn * 64 + nf * 8 + lc * 2;
            int j0 = c6 * 128 + jl0;
            #pragma unroll
            for (int rr = 0; rr < 2; rr++) {
                int il = wm * 16 + rr * 8 + lr;
                int i = m0 + il;
                float o[2];
                #pragma unroll
                for (int jj = 0; jj < 2; jj++) {
                    int j = j0 + jj;
                    int kpos = cc * WW + j - WW;
                    bool ok = (j >= i) && (j <= i + 2 * WW) && (kpos >= 0) && (kpos < SEQ) &&
                              (g_mask[bb * SEQ + kpos] != 0);
                    o[jj] = ok ? acc[nf][rr * 2 + jj] * 0.125f : -30000.f;
                }
                *(__half2*)(&S[il * SP3H + j0]) = __floats2half2_rn(o[0], o[1]);
            }
        }
    }
    __syncthreads();

    {
        int row = tid >> 2, q = tid & 3;
        __half2* Sr = (__half2*)(S + row * SP3H + q * 192);
        float mx = -1e30f;
        #pragma unroll 8
        for (int k = 0; k < 96; k++) {
            float2 f = __half22float2(Sr[k]);
            mx = fmaxf(mx, fmaxf(f.x, f.y));
        }
        mx = fmaxf(mx, __shfl_xor_sync(0xffffffffu, mx, 1));
        mx = fmaxf(mx, __shfl_xor_sync(0xffffffffu, mx, 2));
        float sum = 0.f;
        #pragma unroll 4
        for (int k = 0; k < 96; k++) {
            float2 f = __half22float2(Sr[k]);
            float e0 = expf(f.x - mx), e1 = expf(f.y - mx);
            sum += e0 + e1;
            Sr[k] = __floats2half2_rn(e0, e1);
        }
        sum += __shfl_xor_sync(0xffffffffu, sum, 1);
        sum += __shfl_xor_sync(0xffffffffu, sum, 2);
        float inv = 1.f / sum;
        __half2* op = (__half2*)(g_p + ((size_t)cid * WW + m0 + row) * W3 + q * 192);
        #pragma unroll 8
        for (int k = 0; k < 96; k++) {
            float2 f = __half22float2(Sr[k]);
            op[k] = __floats2half2_rn(f.x * inv, f.y * inv);
        }
    }
}

// ---------------- band attention ctx (fp16 mma + ldmatrix): 128x64, K=768 ----------------
constexpr int CTX_SMEM = (128 * SPITCH + 64 * SPITCH) * 4;   // 27648 B

__global__ void __launch_bounds__(256, 4) ctx_tc_kernel() {
    extern __shared__ uint32_t smc[];
    uint32_t* Ps = smc;
    uint32_t* Vs = smc + 128 * SPITCH;
    __half* Vh = (__half*)Vs;

    const int cid = blockIdx.z;
    const int bb = cid / (NH * NCH);
    const int hh = (cid / NCH) % NH;
    const int cc = cid % NCH;
    const int m0 = blockIdx.y * 128;
    const int tid = threadIdx.x;
    const int wid = tid >> 5, lane = tid & 31;
    const int wm = wid & 3, wn = wid >> 2;
    const int lr = lane >> 2, lc = lane & 3;

    const int lrow = tid >> 1;
    const int lq   = (tid & 1) * 16;
    const int vj = tid & 63;
    const int vd = (tid >> 6) * 16;

    const int arow  = wm * 32 + (lane & 15);
    const int acolw = (lane >> 4) * 4;
    const int bg    = lane >> 3;
    const int brow  = wn * 32 + (bg >> 1) * 8 + (lane & 7);
    const int bcolw = (bg & 1) * 4;
    const uint32_t pb = smem_u32(Ps);
    const uint32_t vb = smem_u32(Vs);

    float acc[2][4][4] = {};

    for (int kt = 0; kt < 12; kt++) {
        const int kb0 = kt * 64;
        {
            const __half* src = g_p + ((size_t)cid * WW + m0 + lrow) * W3 + kb0 + (tid & 1) * 32;
            #pragma unroll
            for (int i = 0; i < 4; i++) {
                uint4 v = *(const uint4*)(src + i * 8);
                *(uint4*)(&Ps[lrow * SPITCH + lq + i * 4]) = v;
            }
        }
        {
            int kpos = cc * WW + kb0 + vj - WW;
            bool in = (kpos >= 0 && kpos < SEQ);
            const __half* vr = g_qkv + (size_t)(bb * SEQ + (in ? kpos : 0)) * QKVS + 2 * DM + hh * DHD;
            #pragma unroll
            for (int q8 = 0; q8 < 2; q8++) {
                int d0 = vd + q8 * 8;
                uint4 vv = in ? *(const uint4*)(vr + d0) : make_uint4(0, 0, 0, 0);
                const __half* hv = (const __half*)&vv;
                #pragma unroll
                for (int e = 0; e < 8; e++)
                    Vh[(d0 + e) * (2 * SPITCH) + vj] = hv[e];
            }
        }
        __syncthreads();

        #pragma unroll
        for (int kk = 0; kk < 4; kk++) {
            const int kb = kk * 8;
            uint32_t afr[2][4];
            #pragma unroll
            for (int mf = 0; mf < 2; mf++)
                ldsm_x4(afr[mf][0], afr[mf][1], afr[mf][2], afr[mf][3],
                        pb + (uint32_t)(((arow + mf * 16) * SPITCH + kb + acolw) * 4));
            #pragma unroll
            for (int p = 0; p < 2; p++) {
                uint32_t b0, b1, b2, b3;
                ldsm_x4(b0, b1, b2, b3,
                        vb + (uint32_t)(((brow + p * 16) * SPITCH + kb + bcolw) * 4));
                uint32_t bfr0[2] = { b0, b1 };
                uint32_t bfr1[2] = { b2, b3 };
                mma_f16(acc[0][p * 2 + 0], afr[0], bfr0);
                mma_f16(acc[1][p * 2 + 0], afr[1], bfr0);
                mma_f16(acc[0][p * 2 + 1], afr[0], bfr1);
                mma_f16(acc[1][p * 2 + 1], afr[1], bfr1);
            }
        }
        __syncthreads();
    }

    #pragma unroll
    for (int mf = 0; mf < 2; mf++) {
        #pragma unroll
        for (int nf = 0; nf < 4; nf++) {
            int i0 = m0 + wm * 32 + mf * 16 + lr;
            int d  = wn * 32 + nf * 8 + lc * 2;
            size_t base0 = (size_t)(bb * SEQ + cc * WW + i0) * DM + hh * DHD + d;
            size_t base1 = (size_t)(bb * SEQ + cc * WW + i0 + 8) * DM + hh * DHD + d;
            *(__half2*)(g_ctx + base0) = __floats2half2_rn(acc[mf][nf][0], acc[mf][nf][1]);
            *(__half2*)(g_ctx + base1) = __floats2half2_rn(acc[mf][nf][2], acc[mf][nf][3]);
        }
    }
}

// ---------------- LSTM (xp prefetch pipelined one step ahead) ----------------
constexpr int LBLK = 12;
constexpr int LJ = 32;
constexpr int LSTM_SMF = HIDN * 128 + 768 + 2048 + 256;

__global__ void lstm_init_kernel() {
    int tid = threadIdx.x;
    if (tid < 2) g_bar[tid] = 0u;
    for (int i = tid; i < 2 * 2 * 2 * HIDN; i += 256)
        ((float*)g_lh)[i] = 0.f;
}

__global__ void lstm_kernel(const float* __restrict__ whf, const float* __restrict__ whb,
                            float* __restrict__ out) {
    extern __shared__ float smf[];
    float* Wh_s = smf;
    float* h_s  = smf + HIDN * 128;
    float* red  = h_s + 768;
    float* gsum = red + 2048;

    int tid = threadIdx.x;
    int dir = blockIdx.x / LBLK;
    int blk = blockIdx.x % LBLK;
    int j0 = blk * LJ;
    const float* Wh = dir ? whb : whf;
    const float* xp = dir ? g_xb : g_xf;

    for (int idx = tid; idx < LJ * 4 * HIDN; idx += 256) {
        int r = idx / HIDN, k = idx % HIDN;
        int jl = r >> 2, gate = r & 3;
        Wh_s[k * 128 + r] = Wh[(size_t)(gate * HIDN + j0 + jl) * HIDN + k];
    }
    __syncthreads();

    int w = tid >> 5, lane = tid & 31;
    int kbeg = w * 48;
    int rjl = tid >> 3, rg = tid & 7;
    int rgate = rg >> 1, rb = rg & 1;
    int jl_u = tid >> 1, b_u = tid & 1;
    float c_state = 0.f;

    const size_t xoff = (size_t)rb * SEQ * (4 * HIDN) + rgate * HIDN + j0 + rjl;
    int s0 = dir ? (SEQ - 1) : 0;
    float xcur = xp[xoff + (size_t)s0 * (4 * HIDN)];

    for (int n = 0; n < SEQ; n++) {
        int s = dir ? (SEQ - 1 - n) : n;
        float xnext = 0.f;
        if (n + 1 < SEQ) {
            int sn = dir ? (SEQ - 2 - n) : (n + 1);
            xnext = xp[xoff + (size_t)sn * (4 * HIDN)];
        }
        for (int i = tid; i < 768; i += 256) h_s[i] = __ldcg(&g_lh[dir][n & 1][i]);
        __syncthreads();

        float a0 = 0, a1 = 0, a2 = 0, a3 = 0, a4 = 0, a5 = 0, a6 = 0, a7 = 0;
        const float* hs0 = h_s;
        const float* hs1 = h_s + HIDN;
        #pragma unroll 4
        for (int kk = 0; kk < 48; kk++) {
            int k = kbeg + kk;
            float4 w4 = *(const float4*)(&Wh_s[k * 128 + lane * 4]);
            float h0 = hs0[k], h1 = hs1[k];
            a0 += w4.x * h0; a1 += w4.x * h1;
            a2 += w4.y * h0; a3 += w4.y * h1;
            a4 += w4.z * h0; a5 += w4.z * h1;
            a6 += w4.w * h0; a7 += w4.w * h1;
        }
        float* rp = red + (w * 256 + lane * 8);
        rp[0] = a0; rp[1] = a1; rp[2] = a2; rp[3] = a3;
        rp[4] = a4; rp[5] = a5; rp[6] = a6; rp[7] = a7;
        __syncthreads();
        {
            float sum = 0.f;
            #pragma unroll
            for (int ww = 0; ww < 8; ww++) sum += red[ww * 256 + rjl * 8 + rg];
            sum += xcur;
            gsum[rjl * 8 + rg] = sum;
        }
        __syncthreads();
        if (tid < 64) {
            float gi = gsum[jl_u * 8 + 0 + b_u];
            float gf = gsum[jl_u * 8 + 2 + b_u];
            float gg = gsum[jl_u * 8 + 4 + b_u];
            float go = gsum[jl_u * 8 + 6 + b_u];
            c_state = sigmoidf_(gf) * c_state + sigmoidf_(gi) * tanhf(gg);
            float hh = sigmoidf_(go) * tanhf(c_state);
            g_lh[dir][(n + 1) & 1][b_u * HIDN + j0 + jl_u] = hh;
            if ((s & 63) == 0)
                out[(size_t)(b_u * 64 + (s >> 6)) * (2 * HIDN) + dir * HIDN + j0 + jl_u] = hh;
        }
        __syncthreads();
        if (tid == 0) {
            __threadfence();
            atomicAdd(&g_bar[dir], 1u);
            unsigned target = (unsigned)(LBLK * (n + 1));
            volatile unsigned* bp = &g_bar[dir];
            while (*bp < target) {}
        }
        __syncthreads();
        xcur = xnext;
    }
}

// ---------------- host launcher ----------------
extern "C" void kernel_launch(void* const* d_in, const int* in_sizes, int n_in,
                              void* d_out, int out_size) {
    const int*   x     = (const int*)d_in[0];
    const float* emb_w = (const float*)d_in[1];
    const float* emb_p = (const float*)d_in[2];
    const float* ln_eg = (const float*)d_in[3];
    const float* ln_eb = (const float*)d_in[4];
    const float* Wq = (const float*)d_in[5];
    const float* bq = (const float*)d_in[6];
    const float* Wk = (const float*)d_in[7];
    const float* bk = (const float*)d_in[8];
    const float* Wv = (const float*)d_in[9];
    const float* bv = (const float*)d_in[10];
    const float* Wo = (const float*)d_in[11];
    const float* bo = (const float*)d_in[12];
    const float* ln1g = (const float*)d_in[13];
    const float* ln1b = (const float*)d_in[14];
    const float* W1 = (const float*)d_in[15];
    const float* bf1 = (const float*)d_in[16];
    const float* W2 = (const float*)d_in[17];
    const float* bf2 = (const float*)d_in[18];
    const float* ln2g = (const float*)d_in[19];
    const float* ln2b = (const float*)d_in[20];
    const float* wi_f = (const float*)d_in[21];
    const float* wh_f = (const float*)d_in[22];
    const float* b_f  = (const float*)d_in[23];
    const float* wi_b = (const float*)d_in[24];
    const float* wh_b = (const float*)d_in[25];
    const float* b_b  = (const float*)d_in[26];
    float* out = (float*)d_out;

    __half *phr, *pqkv, *pctx, *pwT, *pffh;
    float *ph, *pt, *pxf, *pxb, *pbq;
    cudaGetSymbolAddress((void**)&ph,   g_h);
    cudaGetSymbolAddress((void**)&phr,  g_hr);
    cudaGetSymbolAddress((void**)&pqkv, g_qkv);
    cudaGetSymbolAddress((void**)&pctx, g_ctx);
    cudaGetSymbolAddress((void**)&pt,   g_t);
    cudaGetSymbolAddress((void**)&pxf,  g_xf);
    cudaGetSymbolAddress((void**)&pxb,  g_xb);
    cudaGetSymbolAddress((void**)&pwT,  g_wTh);
    cudaGetSymbolAddress((void**)&pffh, g_ffh);
    cudaGetSymbolAddress((void**)&pbq,  g_bqkv);

    cudaFuncSetAttribute(gemm_tc_kernel, cudaFuncAttributeMaxDynamicSharedMemorySize, GTC_SMEM);
    cudaFuncSetAttribute(scores_sm_kernel, cudaFuncAttributeMaxDynamicSharedMemorySize, SSM_SMEM);
    cudaFuncSetAttribute(ctx_tc_kernel, cudaFuncAttributeMaxDynamicSharedMemorySize, CTX_SMEM);

    embed_ln_kernel<<<NROWS, 256>>>(x, emb_w, emb_p, ln_eg, ln_eb);

    dim3 tb(32, 8);
    dim3 tgD(DM / 32, DM / 32);
    dim3 tgW1(FFD / 32, DM / 32);
    dim3 tgW2(DM / 32, FFD / 32);

    dim3 gQKV(QKVS / 256, NROWS / 128);
    dim3 gP(DM / 256, NROWS / 128);
    dim3 gFF1(FFD / 256, NROWS / 128);
    dim3 gX((4 * HIDN) / 256, NROWS / 128);
    dim3 gSc(WW / 64, BATCH * NH * NCH);
    dim3 gCtx(1, WW / 128, BATCH * NH * NCH);

    for (int l = 0; l < NL; l++) {
        transpose_kernel<<<tgD, tb>>>(Wq + (size_t)l * DM * DM, pwT, DM, DM);
        transpose_kernel<<<tgD, tb>>>(Wk + (size_t)l * DM * DM, pwT + (size_t)DM * DM, DM, DM);
        transpose_kernel<<<tgD, tb>>>(Wv + (size_t)l * DM * DM, pwT + (size_t)2 * DM * DM, DM, DM);
        biascat_kernel<<<9, 256>>>(bq + l * DM, bk + l * DM, bv + l * DM);
        gemm_tc_kernel<<<gQKV, 512, GTC_SMEM>>>(phr, pwT, pbq, pqkv, NROWS, QKVS, DM, 0, 1);
        scores_sm_kernel<<<gSc, 256, SSM_SMEM>>>();
        ctx_tc_kernel<<<gCtx, 256, CTX_SMEM>>>();
        transpose_kernel<<<tgD, tb>>>(Wo + (size_t)l * DM * DM, pwT, DM, DM);
        gemm_tc_kernel<<<gP, 512, GTC_SMEM>>>(pctx, pwT, bo + l * DM, pt, NROWS, DM, DM, 0, 0);
        ln_res_kernel<<<NROWS, 256>>>(pt, ln1g + l * DM, ln1b + l * DM);
        transpose_kernel<<<tgW1, tb>>>(W1 + (size_t)l * DM * FFD, pwT, DM, FFD);
        gemm_tc_kernel<<<gFF1, 512, GTC_SMEM>>>(phr, pwT, bf1 + l * FFD, pffh, NROWS, FFD, DM, 1, 1);
        transpose_kernel<<<tgW2, tb>>>(W2 + (size_t)l * FFD * DM, pwT, FFD, DM);
        gemm_tc_kernel<<<gP, 512, GTC_SMEM>>>(pffh, pwT, bf2 + l * DM, pt, NROWS, DM, FFD, 0, 0);
        ln_res_kernel<<<NROWS, 256>>>(pt, ln2g + l * DM, ln2b + l * DM);
    }

    // LSTM input projections (fp16 weights, fp32 outputs)
    int n4 = (4 * HIDN * DM) / 4;
    halfcopy_kernel<<<(n4 + 255) / 256, 256>>>(wi_f, pwT, n4);
    gemm_tc_kernel<<<gX, 512, GTC_SMEM>>>(phr, pwT, b_f, pxf, NROWS, 4 * HIDN, DM, 0, 0);
    halfcopy_kernel<<<(n4 + 255) / 256, 256>>>(wi_b, pwT, n4);
    gemm_tc_kernel<<<gX, 512, GTC_SMEM>>>(phr, pwT, b_b, pxb, NROWS, 4 * HIDN, DM, 0, 0);

    lstm_init_kernel<<<1, 256>>>();
    static_assert(LSTM_SMF * 4 <= 227 * 1024, "smem");
    cudaFuncSetAttribute(lstm_kernel, cudaFuncAttributeMaxDynamicSharedMemorySize, LSTM_SMF * 4);
    lstm_kernel<<<2 * LBLK, 256, LSTM_SMF * 4>>>(wh_f, wh_b, out);
}

// round 17
// speedup vs baseline: 1.0304x; 1.0304x over previous
#include <cuda_runtime.h>
#include <cuda_fp16.h>
#include <math.h>
#include <cstdint>

// ---------------- problem constants ----------------
constexpr int BATCH = 2;
constexpr int SEQ   = 4096;
constexpr int DM    = 768;
constexpr int NH    = 12;
constexpr int DHD   = 64;
constexpr int NL    = 12;
constexpr int WW    = 256;
constexpr int FFD   = 3072;
constexpr int HIDN  = 384;
constexpr int NCH   = SEQ / WW;          // 16 chunks
constexpr int NROWS = BATCH * SEQ;       // 8192
constexpr int W3    = 3 * WW;            // 768
constexpr int QKVS  = 3 * DM;            // 2304

// per-layer transposed-weight block (halves)
constexpr size_t LWT_QKV = (size_t)3 * DM * DM;          // 1769472
constexpr size_t LWT_WO  = (size_t)DM * DM;              // 589824
constexpr size_t LWT_W1  = (size_t)DM * FFD;             // 2359296
constexpr size_t LWT_W2  = (size_t)FFD * DM;             // 2359296
constexpr size_t LWT     = LWT_QKV + LWT_WO + LWT_W1 + LWT_W2;   // 7077888

// ---------------- device scratch (static: no allocation allowed) ----------------
__device__ float g_h  [NROWS * DM];
__device__ __align__(16) __half g_hr [NROWS * DM];
__device__ __align__(16) __half g_qkv[NROWS * QKVS];
__device__ __align__(16) __half g_ctx[NROWS * DM];
__device__ __align__(16) __half g_p  [(size_t)BATCH * NH * NCH * WW * W3];
__device__ __align__(16) __half g_ffh[NROWS * FFD];
__device__ float g_t  [NROWS * DM];
__device__ float g_xf [NROWS * 4 * HIDN];
__device__ float g_xb [NROWS * 4 * HIDN];
__device__ __align__(16) __half g_wTall[NL * LWT];       // all transposed weights (~170MB)
__device__ __align__(16) __half g_wTh[FFD * DM];         // LSTM Wi scratch
__device__ float g_bqkvall[NL * QKVS];
__device__ unsigned char g_mask[NROWS];
__device__ float g_lh [2][2][2 * HIDN];
__device__ unsigned int g_bar[2];

// ---------------- helpers ----------------
__device__ __forceinline__ float sigmoidf_(float x) { return 1.f / (1.f + expf(-x)); }
__device__ __forceinline__ float geluf_(float x)    { return 0.5f * x * (1.f + erff(x * 0.70710678118654752f)); }

__device__ __forceinline__ uint32_t smem_u32(const void* p) {
    uint32_t a;
    asm("{ .reg .u64 t; cvta.to.shared.u64 t, %1; cvt.u32.u64 %0, t; }" : "=r"(a) : "l"(p));
    return a;
}
__device__ __forceinline__ void cp16(uint32_t daddr, const void* src) {
    asm volatile("cp.async.cg.shared.global [%0], [%1], 16;" :: "r"(daddr), "l"(src));
}
__device__ __forceinline__ void ldsm_x4(uint32_t& r0, uint32_t& r1, uint32_t& r2, uint32_t& r3,
                                        uint32_t addr) {
    asm volatile("ldmatrix.sync.aligned.m8n8.x4.shared.b16 {%0,%1,%2,%3}, [%4];"
                 : "=r"(r0), "=r"(r1), "=r"(r2), "=r"(r3) : "r"(addr));
}

__device__ __forceinline__ void mma_f16(float c[4], const uint32_t a[4], const uint32_t b[2]) {
    asm volatile(
        "mma.sync.aligned.m16n8k16.row.col.f32.f16.f16.f32 "
        "{%0,%1,%2,%3}, {%4,%5,%6,%7}, {%8,%9}, {%0,%1,%2,%3};"
        : "+f"(c[0]), "+f"(c[1]), "+f"(c[2]), "+f"(c[3])
        : "r"(a[0]), "r"(a[1]), "r"(a[2]), "r"(a[3]), "r"(b[0]), "r"(b[1]));
}

__device__ __forceinline__ float block_sum256(float v, float* red) {
    #pragma unroll
    for (int o = 16; o; o >>= 1) v += __shfl_xor_sync(0xffffffffu, v, o);
    if ((threadIdx.x & 31) == 0) red[threadIdx.x >> 5] = v;
    __syncthreads();
    float r = red[0] + red[1] + red[2] + red[3] + red[4] + red[5] + red[6] + red[7];
    __syncthreads();
    return r;
}

// ---------------- embedding + layernorm + key_mask ----------------
__global__ void embed_ln_kernel(const int* __restrict__ x, const float* __restrict__ ew,
                                const float* __restrict__ ep, const float* __restrict__ gam,
                                const float* __restrict__ bet) {
    __shared__ float red[8];
    int row = blockIdx.x;
    int tid = threadIdx.x;
    int s = row % SEQ;
    int tok = x[row];
    if (tid == 0) g_mask[row] = (tok != 0) ? 1 : 0;
    float v[3];
    #pragma unroll
    for (int i = 0; i < 3; i++) {
        int c = i * 256 + tid;
        v[i] = ew[(size_t)tok * DM + c] + ep[(size_t)s * DM + c];
    }
    float mean = block_sum256(v[0] + v[1] + v[2], red) * (1.f / DM);
    float var = 0.f;
    #pragma unroll
    for (int i = 0; i < 3; i++) { float d = v[i] - mean; var += d * d; }
    var = block_sum256(var, red) * (1.f / DM);
    float rstd = rsqrtf(var + 1e-5f);
    #pragma unroll
    for (int i = 0; i < 3; i++) {
        int c = i * 256 + tid;
        float o = (v[i] - mean) * rstd * gam[c] + bet[c];
        g_h [(size_t)row * DM + c] = o;
        g_hr[(size_t)row * DM + c] = __float2half_rn(o);
    }
}

// ---------------- residual + layernorm ----------------
__global__ void ln_res_kernel(const float* __restrict__ t, const float* __restrict__ gam,
                              const float* __restrict__ bet) {
    __shared__ float red[8];
    int row = blockIdx.x;
    int tid = threadIdx.x;
    float v[3];
    #pragma unroll
    for (int i = 0; i < 3; i++) {
        int c = i * 256 + tid;
        size_t idx = (size_t)row * DM + c;
        v[i] = g_h[idx] + t[idx];
    }
    float mean = block_sum256(v[0] + v[1] + v[2], red) * (1.f / DM);
    float var = 0.f;
    #pragma unroll
    for (int i = 0; i < 3; i++) { float d = v[i] - mean; var += d * d; }
    var = block_sum256(var, red) * (1.f / DM);
    float rstd = rsqrtf(var + 1e-5f);
    #pragma unroll
    for (int i = 0; i < 3; i++) {
        int c = i * 256 + tid;
        float o = (v[i] - mean) * rstd * gam[c] + bet[c];
        g_h [(size_t)row * DM + c] = o;
        g_hr[(size_t)row * DM + c] = __float2half_rn(o);
    }
}

// ---------------- weight transpose: float in[R][C] -> half out[C][R] ----------------
__global__ void transpose_kernel(const float* __restrict__ in, __half* __restrict__ out,
                                 int R, int C) {
    __shared__ float t[32][33];
    int c0 = blockIdx.x * 32, r0 = blockIdx.y * 32;
    int x = threadIdx.x, y = threadIdx.y;
    #pragma unroll
    for (int i = 0; i < 32; i += 8)
        t[y + i][x] = in[(size_t)(r0 + y + i) * C + c0 + x];
    __syncthreads();
    #pragma unroll
    for (int i = 0; i < 32; i += 8)
        out[(size_t)(c0 + y + i) * R + r0 + x] = __float2half_rn(t[x][y + i]);
}

// ---------------- float -> half copy (LSTM Wi) ----------------
__global__ void halfcopy_kernel(const float* __restrict__ in, __half* __restrict__ out, int n4) {
    int i = blockIdx.x * 256 + threadIdx.x;
    if (i < n4) {
        float4 v = ((const float4*)in)[i];
        __half2* o = (__half2*)out + i * 2;
        o[0] = __floats2half2_rn(v.x, v.y);
        o[1] = __floats2half2_rn(v.z, v.w);
    }
}

// ---------------- bias concat for fused QKV (all layers) ----------------
__global__ void biascat_kernel(const float* __restrict__ a, const float* __restrict__ b,
                               const float* __restrict__ c) {
    int l = blockIdx.y;
    int i = blockIdx.x * 256 + threadIdx.x;
    float* dst = g_bqkvall + (size_t)l * QKVS;
    if (i < DM) dst[i] = a[l * DM + i];
    else if (i < 2 * DM) dst[i] = b[l * DM + i - DM];
    else if (i < 3 * DM) dst[i] = c[l * DM + i - 2 * DM];
}

// ---------------- cp.async 3-stage fp16 GEMM + ldmatrix (128x128, 256 thr) ----------------
constexpr int GPITCH = 36;
constexpr int GSTAGE_U32 = 128 * GPITCH;
constexpr int GSTG = 3;
constexpr int GTC_SMEM = GSTG * 2 * GSTAGE_U32 * 4;    // 110592 B

__global__ void __launch_bounds__(256, 2) gemm_tc_kernel(
    const __half* __restrict__ A, const __half* __restrict__ BT,
    const float* __restrict__ bias, void* __restrict__ Cv,
    int M, int N, int K, int act, int outh) {
    extern __shared__ uint32_t sm[];
    const uint32_t sb = smem_u32(sm);

    const int tid = threadIdx.x;
    const int wid = tid >> 5, lane = tid & 31;
    const int wm = wid & 3, wn = wid >> 2;
    const int lr = lane >> 2, lc = lane & 3;
    const int m0 = blockIdx.y * 128, n0 = blockIdx.x * 128;
    const int lrow = tid >> 1;
    const int lq   = (tid & 1) * 16;
    const int KT = K / 64;

    const int arow  = wm * 32 + (lane & 15);
    const int acolw = (lane >> 4) * 4;
    const int bg    = lane >> 3;
    const int brow  = wn * 64 + (bg >> 1) * 8 + (lane & 7);
    const int bcolw = (bg & 1) * 4;

    const __half* gA = A + (size_t)(m0 + lrow) * K + (tid & 1) * 32;
    const __half* gB = BT + (size_t)(n0 + lrow) * K + (tid & 1) * 32;

    #define GISSUE(st, kt) do {                                                   \
        uint32_t base_ = sb + (uint32_t)(st) * (2 * GSTAGE_U32 * 4);              \
        int kb_ = (kt) * 64;                                                      \
        _Pragma("unroll")                                                         \
        for (int i_ = 0; i_ < 4; i_++) {                                          \
            cp16(base_ + (uint32_t)((lrow * GPITCH + lq + i_ * 4) * 4),           \
                 gA + kb_ + i_ * 8);                                              \
            cp16(base_ + (uint32_t)((GSTAGE_U32 + lrow * GPITCH + lq + i_ * 4) * 4), \
                 gB + kb_ + i_ * 8);                                              \
        } } while (0)

    GISSUE(0, 0);
    asm volatile("cp.async.commit_group;" ::: "memory");
    GISSUE(1, 1);
    asm volatile("cp.async.commit_group;" ::: "memory");

    float acc[2][8][4] = {};
    for (int kt = 0; kt < KT; kt++) {
        asm volatile("cp.async.wait_group 1;" ::: "memory");
        __syncthreads();
        if (kt + 2 < KT) {
            int st = kt + 2; st -= (st / GSTG) * GSTG;
            GISSUE(st, kt + 2);
        }
        asm volatile("cp.async.commit_group;" ::: "memory");

        int cs = kt; cs -= (cs / GSTG) * GSTG;
        const uint32_t abase = sb + (uint32_t)(cs * 2 * GSTAGE_U32) * 4;
        const uint32_t bbase = abase + (uint32_t)GSTAGE_U32 * 4;
        #pragma unroll
        for (int kk = 0; kk < 4; kk++) {
            const int kb = kk * 8;
            uint32_t afr[2][4];
            #pragma unroll
            for (int mf = 0; mf < 2; mf++)
                ldsm_x4(afr[mf][0], afr[mf][1], afr[mf][2], afr[mf][3],
                        abase + (uint32_t)(((arow + mf * 16) * GPITCH + kb + acolw) * 4));
            #pragma unroll
            for (int p = 0; p < 4; p++) {
                uint32_t b0, b1, b2, b3;
                ldsm_x4(b0, b1, b2, b3,
                        bbase + (uint32_t)(((brow + p * 16) * GPITCH + kb + bcolw) * 4));
                uint32_t bfr0[2] = { b0, b1 };
                uint32_t bfr1[2] = { b2, b3 };
                mma_f16(acc[0][p * 2 + 0], afr[0], bfr0);
                mma_f16(acc[1][p * 2 + 0], afr[1], bfr0);
                mma_f16(acc[0][p * 2 + 1], afr[0], bfr1);
                mma_f16(acc[1][p * 2 + 1], afr[1], bfr1);
            }
        }
    }
    #undef GISSUE

    #pragma unroll
    for (int mf = 0; mf < 2; mf++) {
        #pragma unroll
        for (int nf = 0; nf < 8; nf++) {
            int row0 = m0 + wm * 32 + mf * 16 + lr;
            int col  = n0 + wn * 64 + nf * 8 + lc * 2;
            float b0 = bias ? bias[col] : 0.f;
            float b1 = bias ? bias[col + 1] : 0.f;
            float2 v0 = make_float2(acc[mf][nf][0] + b0, acc[mf][nf][1] + b1);
            float2 v1 = make_float2(acc[mf][nf][2] + b0, acc[mf][nf][3] + b1);
            if (act) {
                v0.x = geluf_(v0.x); v0.y = geluf_(v0.y);
                v1.x = geluf_(v1.x); v1.y = geluf_(v1.y);
            }
            if (outh) {
                __half* C = (__half*)Cv;
                *(__half2*)(C + (size_t)row0 * N + col) = __floats2half2_rn(v0.x, v0.y);
                *(__half2*)(C + (size_t)(row0 + 8) * N + col) = __floats2half2_rn(v1.x, v1.y);
            } else {
                float* C = (float*)Cv;
                *(float2*)(C + (size_t)row0 * N + col) = v0;
                *(float2*)(C + (size_t)(row0 + 8) * N + col) = v1;
            }
        }
    }
}

// ---------------- fused scores + softmax: 64-row tile, full 768-wide row in smem ----------------
constexpr int SPITCH = 36;
constexpr int SP3H   = 776;
constexpr int SSM_SMEM = (64 * SPITCH + 128 * SPITCH) * 4 + 64 * SP3H * 2;  // 126976 B

__global__ void __launch_bounds__(256, 1) scores_sm_kernel() {
    extern __shared__ uint32_t smq[];
    uint32_t* Qw = smq;
    uint32_t* Kw = smq + 64 * SPITCH;
    __half*  S  = (__half*)(smq + 64 * SPITCH + 128 * SPITCH);

    const int cid = blockIdx.y;
    const int bb = cid / (NH * NCH);
    const int hh = (cid / NCH) % NH;
    const int cc = cid % NCH;
    const int m0 = blockIdx.x * 64;
    const int tid = threadIdx.x;
    const int wid = tid >> 5, lane = tid & 31;
    const int wm = wid & 3, wn = wid >> 2;
    const int lr = lane >> 2, lc = lane & 3;

    const int arow  = wm * 16 + (lane & 15);
    const int acolw = (lane >> 4) * 4;
    const int bg    = lane >> 3;
    const int browb = wn * 64 + (bg >> 1) * 8 + (lane & 7);
    const int bcolw = (bg & 1) * 4;
    const uint32_t qb  = smem_u32(Qw);
    const uint32_t kbb = smem_u32(Kw);

    {
        int row = tid >> 2, seg = tid & 3;
        const __half* src = g_qkv + (size_t)(bb * SEQ + cc * WW + m0 + row) * QKVS + hh * DHD + seg * 16;
        uint4 v0 = *(const uint4*)(src);
        uint4 v1 = *(const uint4*)(src + 8);
        *(uint4*)(&Qw[row * SPITCH + seg * 8 + 0]) = v0;
        *(uint4*)(&Qw[row * SPITCH + seg * 8 + 4]) = v1;
    }

    for (int c6 = 0; c6 < 6; c6++) {
        if (c6 > 0) __syncthreads();
        {
            int krow = tid >> 1;
            int kq = (tid & 1) * 16;
            int kpos = cc * WW + c6 * 128 + krow - WW;
            bool in = (kpos >= 0 && kpos < SEQ);
            const __half* src = g_qkv + (size_t)(bb * SEQ + (in ? kpos : 0)) * QKVS + DM + hh * DHD + (tid & 1) * 32;
            #pragma unroll
            for (int i = 0; i < 4; i++) {
                uint4 v = in ? *(const uint4*)(src + i * 8) : make_uint4(0, 0, 0, 0);
                *(uint4*)(&Kw[krow * SPITCH + kq + i * 4]) = v;
            }
        }
        __syncthreads();

        float acc[8][4] = {};
        #pragma unroll
        for (int kk = 0; kk < 4; kk++) {
            const int kb = kk * 8;
            uint32_t afr[4];
            ldsm_x4(afr[0], afr[1], afr[2], afr[3],
                    qb + (uint32_t)((arow * SPITCH + kb + acolw) * 4));
            #pragma unroll
            for (int p = 0; p < 4; p++) {
                uint32_t b0, b1, b2, b3;
                ldsm_x4(b0, b1, b2, b3,
                        kbb + (uint32_t)(((browb + p * 16) * SPITCH + kb + bcolw) * 4));
                uint32_t bfr0[2] = { b0, b1 };
                uint32_t bfr1[2] = { b2, b3 };
                mma_f16(acc[p * 2 + 0], afr, bfr0);
                mma_f16(acc[p * 2 + 1], afr, bfr1);
            }
        }

        #pragma unroll
        for (int nf = 0; nf < 8; nf++) {
            int jl0 = wn * 64 + nf * 8 + lc * 2;
            int j0 = c6 * 128 + jl0;
            #pragma unroll
            for (int rr = 0; rr < 2; rr++) {
                int il = wm * 16 + rr * 8 + lr;
                int i = m0 + il;
                float o[2];
                #pragma unroll
                for (int jj = 0; jj < 2; jj++) {
                    int j = j0 + jj;
                    int kpos = cc * WW + j - WW;
                    bool ok = (j >= i) && (j <= i + 2 * WW) && (kpos >= 0) && (kpos < SEQ) &&
                              (g_mask[bb * SEQ + kpos] != 0);
                    o[jj] = ok ? acc[nf][rr * 2 + jj] * 0.125f : -30000.f;
                }
                *(__half2*)(&S[il * SP3H + j0]) = __floats2half2_rn(o[0], o[1]);
            }
        }
    }
    __syncthreads();

    {
        int row = tid >> 2, q = tid & 3;
        __half2* Sr = (__half2*)(S + row * SP3H + q * 192);
        float mx = -1e30f;
        #pragma unroll 8
        for (int k = 0; k < 96; k++) {
            float2 f = __half22float2(Sr[k]);
            mx = fmaxf(mx, fmaxf(f.x, f.y));
        }
        mx = fmaxf(mx, __shfl_xor_sync(0xffffffffu, mx, 1));
        mx = fmaxf(mx, __shfl_xor_sync(0xffffffffu, mx, 2));
        float sum = 0.f;
        #pragma unroll 4
        for (int k = 0; k < 96; k++) {
            float2 f = __half22float2(Sr[k]);
            float e0 = expf(f.x - mx), e1 = expf(f.y - mx);
            sum += e0 + e1;
            Sr[k] = __floats2half2_rn(e0, e1);
        }
        sum += __shfl_xor_sync(0xffffffffu, sum, 1);
        sum += __shfl_xor_sync(0xffffffffu, sum, 2);
        float inv = 1.f / sum;
        __half2* op = (__half2*)(g_p + ((size_t)cid * WW + m0 + row) * W3 + q * 192);
        #pragma unroll 8
        for (int k = 0; k < 96; k++) {
            float2 f = __half22float2(Sr[k]);
            op[k] = __floats2half2_rn(f.x * inv, f.y * inv);
        }
    }
}

// ---------------- band attention ctx (fp16 mma + ldmatrix): 128x64, K=768 ----------------
constexpr int CTX_SMEM = (128 * SPITCH + 64 * SPITCH) * 4;

__global__ void __launch_bounds__(256, 4) ctx_tc_kernel() {
    extern __shared__ uint32_t smc[];
    uint32_t* Ps = smc;
    uint32_t* Vs = smc + 128 * SPITCH;
    __half* Vh = (__half*)Vs;

    const int cid = blockIdx.z;
    const int bb = cid / (NH * NCH);
    const int hh = (cid / NCH) % NH;
    const int cc = cid % NCH;
    const int m0 = blockIdx.y * 128;
    const int tid = threadIdx.x;
    const int wid = tid >> 5, lane = tid & 31;
    const int wm = wid & 3, wn = wid >> 2;
    const int lr = lane >> 2, lc = lane & 3;

    const int lrow = tid >> 1;
    const int lq   = (tid & 1) * 16;
    const int vj = tid & 63;
    const int vd = (tid >> 6) * 16;

    const int arow  = wm * 32 + (lane & 15);
    const int acolw = (lane >> 4) * 4;
    const int bg    = lane >> 3;
    const int brow  = wn * 32 + (bg >> 1) * 8 + (lane & 7);
    const int bcolw = (bg & 1) * 4;
    const uint32_t pb = smem_u32(Ps);
    const uint32_t vb = smem_u32(Vs);

    float acc[2][4][4] = {};

    for (int kt = 0; kt < 12; kt++) {
        const int kb0 = kt * 64;
        {
            const __half* src = g_p + ((size_t)cid * WW + m0 + lrow) * W3 + kb0 + (tid & 1) * 32;
            #pragma unroll
            for (int i = 0; i < 4; i++) {
                uint4 v = *(const uint4*)(src + i * 8);
                *(uint4*)(&Ps[lrow * SPITCH + lq + i * 4]) = v;
            }
        }
        {
            int kpos = cc * WW + kb0 + vj - WW;
            bool in = (kpos >= 0 && kpos < SEQ);
            const __half* vr = g_qkv + (size_t)(bb * SEQ + (in ? kpos : 0)) * QKVS + 2 * DM + hh * DHD;
            #pragma unroll
            for (int q8 = 0; q8 < 2; q8++) {
                int d0 = vd + q8 * 8;
                uint4 vv = in ? *(const uint4*)(vr + d0) : make_uint4(0, 0, 0, 0);
                const __half* hv = (const __half*)&vv;
                #pragma unroll
                for (int e = 0; e < 8; e++)
                    Vh[(d0 + e) * (2 * SPITCH) + vj] = hv[e];
            }
        }
        __syncthreads();

        #pragma unroll
        for (int kk = 0; kk < 4; kk++) {
            const int kb = kk * 8;
            uint32_t afr[2][4];
            #pragma unroll
            for (int mf = 0; mf < 2; mf++)
                ldsm_x4(afr[mf][0], afr[mf][1], afr[mf][2], afr[mf][3],
                        pb + (uint32_t)(((arow + mf * 16) * SPITCH + kb + acolw) * 4));
            #pragma unroll
            for (int p = 0; p < 2; p++) {
                uint32_t b0, b1, b2, b3;
                ldsm_x4(b0, b1, b2, b3,
                        vb + (uint32_t)(((brow + p * 16) * SPITCH + kb + bcolw) * 4));
                uint32_t bfr0[2] = { b0, b1 };
                uint32_t bfr1[2] = { b2, b3 };
                mma_f16(acc[0][p * 2 + 0], afr[0], bfr0);
                mma_f16(acc[1][p * 2 + 0], afr[1], bfr0);
                mma_f16(acc[0][p * 2 + 1], afr[0], bfr1);
                mma_f16(acc[1][p * 2 + 1], afr[1], bfr1);
            }
        }
        __syncthreads();
    }

    #pragma unroll
    for (int mf = 0; mf < 2; mf++) {
        #pragma unroll
        for (int nf = 0; nf < 4; nf++) {
            int i0 = m0 + wm * 32 + mf * 16 + lr;
            int d  = wn * 32 + nf * 8 + lc * 2;
            size_t base0 = (size_t)(bb * SEQ + cc * WW + i0) * DM + hh * DHD + d;
            size_t base1 = (size_t)(bb * SEQ + cc * WW + i0 + 8) * DM + hh * DHD + d;
            *(__half2*)(g_ctx + base0) = __floats2half2_rn(acc[mf][nf][0], acc[mf][nf][1]);
            *(__half2*)(g_ctx + base1) = __floats2half2_rn(acc[mf][nf][2], acc[mf][nf][3]);
        }
    }
}

// ---------------- LSTM ----------------
constexpr int LBLK = 12;
constexpr int LJ = 32;
constexpr int LSTM_SMF = HIDN * 128 + 768 + 2048 + 256;

__global__ void lstm_init_kernel() {
    int tid = threadIdx.x;
    if (tid < 2) g_bar[tid] = 0u;
    for (int i = tid; i < 2 * 2 * 2 * HIDN; i += 256)
        ((float*)g_lh)[i] = 0.f;
}

__global__ void lstm_kernel(const float* __restrict__ whf, const float* __restrict__ whb,
                            float* __restrict__ out) {
    extern __shared__ float smf[];
    float* Wh_s = smf;
    float* h_s  = smf + HIDN * 128;
    float* red  = h_s + 768;
    float* gsum = red + 2048;

    int tid = threadIdx.x;
    int dir = blockIdx.x / LBLK;
    int blk = blockIdx.x % LBLK;
    int j0 = blk * LJ;
    const float* Wh = dir ? whb : whf;
    const float* xp = dir ? g_xb : g_xf;

    for (int idx = tid; idx < LJ * 4 * HIDN; idx += 256) {
        int r = idx / HIDN, k = idx % HIDN;
        int jl = r >> 2, gate = r & 3;
        Wh_s[k * 128 + r] = Wh[(size_t)(gate * HIDN + j0 + jl) * HIDN + k];
    }
    __syncthreads();

    int w = tid >> 5, lane = tid & 31;
    int kbeg = w * 48;
    int rjl = tid >> 3, rg = tid & 7;
    int rgate = rg >> 1, rb = rg & 1;
    int jl_u = tid >> 1, b_u = tid & 1;
    float c_state = 0.f;

    const size_t xoff = (size_t)rb * SEQ * (4 * HIDN) + rgate * HIDN + j0 + rjl;
    int s0 = dir ? (SEQ - 1) : 0;
    float xcur = xp[xoff + (size_t)s0 * (4 * HIDN)];

    for (int n = 0; n < SEQ; n++) {
        int s = dir ? (SEQ - 1 - n) : n;
        float xnext = 0.f;
        if (n + 1 < SEQ) {
            int sn = dir ? (SEQ - 2 - n) : (n + 1);
            xnext = xp[xoff + (size_t)sn * (4 * HIDN)];
        }
        for (int i = tid; i < 768; i += 256) h_s[i] = __ldcg(&g_lh[dir][n & 1][i]);
        __syncthreads();

        float a0 = 0, a1 = 0, a2 = 0, a3 = 0, a4 = 0, a5 = 0, a6 = 0, a7 = 0;
        const float* hs0 = h_s;
        const float* hs1 = h_s + HIDN;
        #pragma unroll 4
        for (int kk = 0; kk < 48; kk++) {
            int k = kbeg + kk;
            float4 w4 = *(const float4*)(&Wh_s[k * 128 + lane * 4]);
            float h0 = hs0[k], h1 = hs1[k];
            a0 += w4.x * h0; a1 += w4.x * h1;
            a2 += w4.y * h0; a3 += w4.y * h1;
            a4 += w4.z * h0; a5 += w4.z * h1;
            a6 += w4.w * h0; a7 += w4.w * h1;
        }
        float* rp = red + (w * 256 + lane * 8);
        rp[0] = a0; rp[1] = a1; rp[2] = a2; rp[3] = a3;
        rp[4] = a4; rp[5] = a5; rp[6] = a6; rp[7] = a7;
        __syncthreads();
        {
            float sum = 0.f;
            #pragma unroll
            for (int ww = 0; ww < 8; ww++) sum += red[ww * 256 + rjl * 8 + rg];
            sum += xcur;
            gsum[rjl * 8 + rg] = sum;
        }
        __syncthreads();
        if (tid < 64) {
            float gi = gsum[jl_u * 8 + 0 + b_u];
            float gf = gsum[jl_u * 8 + 2 + b_u];
            float gg = gsum[jl_u * 8 + 4 + b_u];
            float go = gsum[jl_u * 8 + 6 + b_u];
            c_state = sigmoidf_(gf) * c_state + sigmoidf_(gi) * tanhf(gg);
            float hh = sigmoidf_(go) * tanhf(c_state);
            g_lh[dir][(n + 1) & 1][b_u * HIDN + j0 + jl_u] = hh;
            if ((s & 63) == 0)
                out[(size_t)(b_u * 64 + (s >> 6)) * (2 * HIDN) + dir * HIDN + j0 + jl_u] = hh;
        }
        __syncthreads();
        if (tid == 0) {
            __threadfence();
            atomicAdd(&g_bar[dir], 1u);
            unsigned target = (unsigned)(LBLK * (n + 1));
            volatile unsigned* bp = &g_bar[dir];
            while (*bp < target) {}
        }
        __syncthreads();
        xcur = xnext;
    }
}

// ---------------- host launcher ----------------
extern "C" void kernel_launch(void* const* d_in, const int* in_sizes, int n_in,
                              void* d_out, int out_size) {
    const int*   x     = (const int*)d_in[0];
    const float* emb_w = (const float*)d_in[1];
    const float* emb_p = (const float*)d_in[2];
    const float* ln_eg = (const float*)d_in[3];
    const float* ln_eb = (const float*)d_in[4];
    const float* Wq = (const float*)d_in[5];
    const float* bq = (const float*)d_in[6];
    const float* Wk = (const float*)d_in[7];
    const float* bk = (const float*)d_in[8];
    const float* Wv = (const float*)d_in[9];
    const float* bv = (const float*)d_in[10];
    const float* Wo = (const float*)d_in[11];
    const float* bo = (const float*)d_in[12];
    const float* ln1g = (const float*)d_in[13];
    const float* ln1b = (const float*)d_in[14];
    const float* W1 = (const float*)d_in[15];
    const float* bf1 = (const float*)d_in[16];
    const float* W2 = (const float*)d_in[17];
    const float* bf2 = (const float*)d_in[18];
    const float* ln2g = (const float*)d_in[19];
    const float* ln2b = (const float*)d_in[20];
    const float* wi_f = (const float*)d_in[21];
    const float* wh_f = (const float*)d_in[22];
    const float* b_f  = (const float*)d_in[23];
    const float* wi_b = (const float*)d_in[24];
    const float* wh_b = (const float*)d_in[25];
    const float* b_b  = (const float*)d_in[26];
    float* out = (float*)d_out;

    __half *phr, *pqkv, *pctx, *pwA, *pwT, *pffh;
    float *ph, *pt, *pxf, *pxb, *pbq;
    cudaGetSymbolAddress((void**)&ph,   g_h);
    cudaGetSymbolAddress((void**)&phr,  g_hr);
    cudaGetSymbolAddress((void**)&pqkv, g_qkv);
    cudaGetSymbolAddress((void**)&pctx, g_ctx);
    cudaGetSymbolAddress((void**)&pt,   g_t);
    cudaGetSymbolAddress((void**)&pxf,  g_xf);
    cudaGetSymbolAddress((void**)&pxb,  g_xb);
    cudaGetSymbolAddress((void**)&pwA,  g_wTall);
    cudaGetSymbolAddress((void**)&pwT,  g_wTh);
    cudaGetSymbolAddress((void**)&pffh, g_ffh);
    cudaGetSymbolAddress((void**)&pbq,  g_bqkvall);

    cudaFuncSetAttribute(gemm_tc_kernel, cudaFuncAttributeMaxDynamicSharedMemorySize, GTC_SMEM);
    cudaFuncSetAttribute(scores_sm_kernel, cudaFuncAttributeMaxDynamicSharedMemorySize, SSM_SMEM);
    cudaFuncSetAttribute(ctx_tc_kernel, cudaFuncAttributeMaxDynamicSharedMemorySize, CTX_SMEM);

    embed_ln_kernel<<<NROWS, 256>>>(x, emb_w, emb_p, ln_eg, ln_eb);

    dim3 tb(32, 8);
    dim3 tgD(DM / 32, DM / 32);
    dim3 tgW1(FFD / 32, DM / 32);
    dim3 tgW2(DM / 32, FFD / 32);

    // ---- pre-loop: all weight transposes + bias concat (dense, overlapping) ----
    for (int l = 0; l < NL; l++) {
        __half* wl = pwA + (size_t)l * LWT;
        transpose_kernel<<<tgD, tb>>>(Wq + (size_t)l * DM * DM, wl, DM, DM);
        transpose_kernel<<<tgD, tb>>>(Wk + (size_t)l * DM * DM, wl + (size_t)DM * DM, DM, DM);
        transpose_kernel<<<tgD, tb>>>(Wv + (size_t)l * DM * DM, wl + (size_t)2 * DM * DM, DM, DM);
        transpose_kernel<<<tgD, tb>>>(Wo + (size_t)l * DM * DM, wl + LWT_QKV, DM, DM);
        transpose_kernel<<<tgW1, tb>>>(W1 + (size_t)l * DM * FFD, wl + LWT_QKV + LWT_WO, DM, FFD);
        transpose_kernel<<<tgW2, tb>>>(W2 + (size_t)l * FFD * DM, wl + LWT_QKV + LWT_WO + LWT_W1, FFD, DM);
    }
    biascat_kernel<<<dim3(9, NL), 256>>>(bq, bk, bv);

    dim3 gQKV(QKVS / 128, NROWS / 128);
    dim3 gP(DM / 128, NROWS / 128);
    dim3 gFF1(FFD / 128, NROWS / 128);
    dim3 gX((4 * HIDN) / 128, NROWS / 128);
    dim3 gSc(WW / 64, BATCH * NH * NCH);
    dim3 gCtx(1, WW / 128, BATCH * NH * NCH);

    for (int l = 0; l < NL; l++) {
        __half* wl = pwA + (size_t)l * LWT;
        gemm_tc_kernel<<<gQKV, 256, GTC_SMEM>>>(phr, wl, pbq + (size_t)l * QKVS, pqkv, NROWS, QKVS, DM, 0, 1);
        scores_sm_kernel<<<gSc, 256, SSM_SMEM>>>();
        ctx_tc_kernel<<<gCtx, 256, CTX_SMEM>>>();
        gemm_tc_kernel<<<gP, 256, GTC_SMEM>>>(pctx, wl + LWT_QKV, bo + l * DM, pt, NROWS, DM, DM, 0, 0);
        ln_res_kernel<<<NROWS, 256>>>(pt, ln1g + l * DM, ln1b + l * DM);
        gemm_tc_kernel<<<gFF1, 256, GTC_SMEM>>>(phr, wl + LWT_QKV + LWT_WO, bf1 + l * FFD, pffh, NROWS, FFD, DM, 1, 1);
        gemm_tc_kernel<<<gP, 256, GTC_SMEM>>>(pffh, wl + LWT_QKV + LWT_WO + LWT_W1, bf2 + l * DM, pt, NROWS, DM, FFD, 0, 0);
        ln_res_kernel<<<NROWS, 256>>>(pt, ln2g + l * DM, ln2b + l * DM);
    }

    // LSTM input projections (fp16 weights, fp32 outputs)
    int n4 = (4 * HIDN * DM) / 4;
    halfcopy_kernel<<<(n4 + 255) / 256, 256>>>(wi_f, pwT, n4);
    gemm_tc_kernel<<<gX, 256, GTC_SMEM>>>(phr, pwT, b_f, pxf, NROWS, 4 * HIDN, DM, 0, 0);
    halfcopy_kernel<<<(n4 + 255) / 256, 256>>>(wi_b, pwT + (size_t)2 * HIDN * DM, n4);
    gemm_tc_kernel<<<gX, 256, GTC_SMEM>>>(phr, pwT + (size_t)2 * HIDN * DM, b_b, pxb, NROWS, 4 * HIDN, DM, 0, 0);

    lstm_init_kernel<<<1, 256>>>();
    static_assert(LSTM_SMF * 4 <= 227 * 1024, "smem");
    cudaFuncSetAttribute(lstm_kernel, cudaFuncAttributeMaxDynamicSharedMemorySize, LSTM_SMF * 4);
    lstm_kernel<<<2 * LBLK, 256, LSTM_SMF * 4>>>(wh_f, wh_b, out);
}